// round 11
// baseline (speedup 1.0000x reference)
#include <cuda_runtime.h>
#include <math.h>

#define NS 4096
#define NT 4096
#define RB 16              // interior rows per block chunk
#define WPB 4              // warps per block (128 threads)
#define GX 8               // 8 blocks * 4 warps * 128 cols = 4096 columns
#define GY 256             // 256 chunks * 16 rows >= 4094 interior rows
#define NPART (GX * GY)    // 2048 blocks

__device__ double g_partials[NPART];
__device__ unsigned int g_count;   // zero-init at load; reset by last block each call

// fp32 depressed-cubic hyperbolic root (faithful port of reference formula)
__device__ __forceinline__ float cubicf(float Q) {
    float q   = 6.0f * Q;                                   // CHI * Q
    float arg = fabsf(q) * (1.0f / 5.656854249492381f);     // / (4*sqrt(2))
    arg = fmaxf(arg, 1.0f);
    float c = 4.898979485566356f * coshf(acoshf(arg) * (1.0f / 3.0f)); // 2*sqrt(6)
    return (q >= 0.0f) ? -c : c;
}

// one column of the residual; all FD constants pre-folded
__device__ __forceinline__ void col_body(float upv, float ccv, float dnv,
                                         float lf, float rt, float4 cf, float& acc) {
    float s   = dnv + upv;
    float d   = dnv - upv;
    float w   = fmaf(-2.0f, ccv, s);
    float vss = fmaf(-d, cf.y, w * cf.x);
    vss = fminf(fmaxf(vss, -100.0f), 100.0f);
    float res = fmaf(rt - lf, 102375.0f,
                fmaf(-cf.z, vss,
                fmaf(-cf.w, d, 2.5f * ccv)));
    acc = fmaf(res, res, acc);
}

__global__ __launch_bounds__(128, 8) void fused_kernel(const float* __restrict__ V,
                                                       float* __restrict__ out) {
    __shared__ float4 scoef[RB];
    __shared__ double wsum[WPB];
    __shared__ double sbt;
    __shared__ int    slast;

    const int tid  = threadIdx.x;
    const int lane = tid & 31;
    const int warp = tid >> 5;
    const int bid  = blockIdx.y * GX + blockIdx.x;
    const int W    = blockIdx.x * WPB + warp;
    const int jbase = W * 128;
    const int j0    = jbase + 4 * lane;
    const bool isL  = (lane == 0);
    const bool isR  = (lane == 31);
    const bool needH = isL || isR;
    int haddr = isL ? (jbase - 1) : (jbase + 128);
    haddr = min(max(haddr, 0), NT - 1);

    const float m0 = (j0 >= 1) ? 1.0f : 0.0f;
    const float m3 = (j0 + 3 <= NT - 2) ? 1.0f : 0.0f;

    const int ib = 1 + blockIdx.y * RB;                 // first interior row of chunk

    const float* __restrict__ Vj = V + j0;
    const float* __restrict__ Vh = V + haddr;

    // ---- issue preloads immediately (cover the coef computation below) ----
    float4 up = *(const float4*)(Vj + (size_t)(ib - 1) * NT);
    float4 cc = *(const float4*)(Vj + (size_t)ib * NT);
    float  hc = needH ? Vh[(size_t)ib * NT] : 0.0f;
    float4 n1 = *(const float4*)(Vj + (size_t)(ib + 1) * NT);
    float  h1 = needH ? Vh[(size_t)(ib + 1) * NT] : 0.0f;
    const int r2 = min(ib + 2, NS - 1);
    float4 n2 = *(const float4*)(Vj + (size_t)r2 * NT);
    float  h2 = needH ? Vh[(size_t)r2 * NT] : 0.0f;

    // ---- per-block coefficient table (folded constants), overlapped with loads ----
    if (tid < RB) {
        const float C1 = cubicf(100.0f / 30.0f);        // (B - 0)/ALPHA_STR
        const float C2 = cubicf(-200.0f / 30.0f);       // (B - S_MAX)/ALPHA_STR
        const int   i  = min(ib + tid, NS - 1);
        const float u  = (float)i * (1.0f / 4095.0f);
        const float L  = C2 * u + C1 * (1.0f - u);
        const float dL = C2 - C1;
        const float S   = 100.0f + 30.0f * (L * L * L * (1.0f / 6.0f) + L);
        const float dS  = 30.0f * dL * (0.5f * L * L + 1.0f);
        const float d2S = 30.0f * dL * dL * L;
        const float Sn  = S   * (1.0f / 300.0f);
        const float Su  = dS  * (1.0f / 300.0f);
        const float Suu = d2S * (1.0f / 300.0f);
        float4 c;
        c.x = 16769025.0f / (Su * Su);                 // 1/DU^2 folded
        c.y = 2047.5f * Suu / (Su * Su * Su);          // 1/(2DU) folded
        c.z = Sn * Sn;                                 // S_norm^2
        c.w = 2047.5f * 2.5f * Sn / Su;                // 1/(2DU)*ALPHA*Sn/Su
        scoef[tid] = c;
    }
    __syncthreads();

    float a0 = 0.0f, a1 = 0.0f, a2 = 0.0f, a3 = 0.0f;

    if (blockIdx.y < GY - 1) {
        // ================= FAST PATH =================
        // all rows interior (max prefetch row = ib+RB+2 <= 4083 < 4095): no clamps,
        // no validity checks, pure pointer-bump addressing.
        const float* pr = Vj + (size_t)(ib + 3) * NT;   // next row to load
        const float* ph = Vh + (size_t)(ib + 3) * NT;

#pragma unroll 8
        for (int k = 0; k < RB; k++) {
            const float4 dn = n1;  const float hd = h1;
            n1 = n2;               h1 = h2;
            n2 = *(const float4*)pr;
            h2 = needH ? *ph : 0.0f;
            pr += NT;  ph += NT;

            float lf0 = __shfl_up_sync(0xffffffffu, cc.w, 1);
            float rt3 = __shfl_down_sync(0xffffffffu, cc.x, 1);
            if (isL) lf0 = hc;
            if (isR) rt3 = hc;

            const float4 cf = scoef[k];
            col_body(up.x, cc.x, dn.x, lf0,  cc.y, cf, a0);
            col_body(up.y, cc.y, dn.y, cc.x, cc.z, cf, a1);
            col_body(up.z, cc.z, dn.z, cc.y, cc.w, cf, a2);
            col_body(up.w, cc.w, dn.w, cc.z, rt3,  cf, a3);

            up = cc; cc = dn; hc = hd;
        }
    } else {
        // ================= BOUNDARY PATH (8 blocks) =================
#pragma unroll 4
        for (int k = 0; k < RB; k++) {
            const int i = ib + k;
            const float4 dn = n1;  const float hd = h1;
            n1 = n2;               h1 = h2;
            const int rp = min(i + 3, NS - 1);
            n2 = *(const float4*)(Vj + (size_t)rp * NT);
            h2 = needH ? Vh[(size_t)rp * NT] : 0.0f;

            float lf0 = __shfl_up_sync(0xffffffffu, cc.w, 1);
            float rt3 = __shfl_down_sync(0xffffffffu, cc.x, 1);
            if (isL) lf0 = hc;
            if (isR) rt3 = hc;

            if (i <= NS - 2) {
                const float4 cf = scoef[k];
                col_body(up.x, cc.x, dn.x, lf0,  cc.y, cf, a0);
                col_body(up.y, cc.y, dn.y, cc.x, cc.z, cf, a1);
                col_body(up.z, cc.z, dn.z, cc.y, cc.w, cf, a2);
                col_body(up.w, cc.w, dn.w, cc.z, rt3,  cf, a3);
            }
            up = cc; cc = dn; hc = hd;
        }
    }

    // boundary columns masked once (iteration-invariant; all values finite)
    a0 *= m0;
    a3 *= m3;

    // ---- BC row + TC column: 2 elements each per block (2048 * 2 = 4096) ----
    if (warp == WPB - 1) {
        double extra = 0.0;
        if (lane < 2) {
            const int jj = 2 * bid + lane;
            float t      = (float)jj * (1.0f / 4095.0f);
            float target = 1.0f - (100.0f / 300.0f) * expf(-0.05f * (1.0f - t));
            float d      = V[(size_t)(NS - 1) * NT + jj] - target;
            extra = (double)(d * d) * (10.0 / 4096.0);
        } else if (lane >= 8 && lane < 10) {
            const int ii = 2 * bid + (lane - 8);
            float u  = (float)ii * (1.0f / 4095.0f);
            float x  = 50.0f * (u - (100.0f / 300.0f));
            float sp = fmaxf(x, 0.0f) + log1pf(expf(-fabsf(x)));
            float payoff = sp * (1.0f / 50.0f);
            float d  = V[(size_t)ii * NT + (NT - 1)] - payoff;
            float ad = fabsf(d);
            float h  = (ad < 0.01f) ? 0.5f * d * d : 0.01f * (ad - 0.005f);
            extra = (double)h * (10.0 / 4096.0);
        }
        for (int o = 16; o; o >>= 1) extra += __shfl_xor_sync(0xffffffffu, extra, o);
        if (lane == 0) sbt = extra;
    }

    // ---- block reduction -> double partial ----
    float acc = (a0 + a1) + (a2 + a3);
    for (int o = 16; o; o >>= 1) acc += __shfl_xor_sync(0xffffffffu, acc, o);
    if (lane == 0) wsum[warp] = (double)acc;
    __syncthreads();

    if (tid == 0) {
        double s = 0.0;
#pragma unroll
        for (int w = 0; w < WPB; w++) s += wsum[w];
        const double n_int = (double)(NS - 2) * (double)(NT - 2);
        g_partials[bid] = s / n_int + sbt;
        __threadfence();
        unsigned int old = atomicAdd(&g_count, 1u);
        slast = (old == NPART - 1) ? 1 : 0;
    }
    __syncthreads();

    // ---- last block: final reduction over 2048 doubles ----
    if (slast) {
        double s = 0.0;
#pragma unroll
        for (int p = 0; p < NPART / 128; p++) s += g_partials[p * 128 + tid];
        __shared__ double sred[128];
        sred[tid] = s;
        __syncthreads();
        for (int o = 64; o; o >>= 1) {
            if (tid < o) sred[tid] += sred[tid + o];
            __syncthreads();
        }
        if (tid == 0) {
            out[0] = (float)sred[0];
            g_count = 0;                     // reset for next graph replay
        }
    }
}

extern "C" void kernel_launch(void* const* d_in, const int* in_sizes, int n_in,
                              void* d_out, int out_size) {
    const float* V = (const float*)d_in[0];
    float* out = (float*)d_out;
    fused_kernel<<<dim3(GX, GY), WPB * 32>>>(V, out);
}

// round 12
// speedup vs baseline: 1.1199x; 1.1199x over previous
#include <cuda_runtime.h>
#include <math.h>

#define NS 4096
#define NT 4096
#define RB 32              // interior rows per block chunk
#define WPB 4              // warps per block (128 threads)
#define GX 8               // 8 blocks * 4 warps * 128 cols = 4096 columns
#define GY 128             // 128 chunks * 32 rows >= 4094 interior rows
#define NPART (GX * GY)    // 1024 blocks

__device__ double g_partials[NPART];
__device__ unsigned int g_count;   // zero-init at load; reset by last block each call

// fp32 depressed-cubic hyperbolic root (faithful port of reference formula)
__device__ __forceinline__ float cubicf(float Q) {
    float q   = 6.0f * Q;                                   // CHI * Q
    float arg = fabsf(q) * (1.0f / 5.656854249492381f);     // / (4*sqrt(2))
    arg = fmaxf(arg, 1.0f);
    float c = 4.898979485566356f * coshf(acoshf(arg) * (1.0f / 3.0f)); // 2*sqrt(6)
    return (q >= 0.0f) ? -c : c;
}

// one column of the residual; all FD constants pre-folded
__device__ __forceinline__ void col_body(float upv, float ccv, float dnv,
                                         float lf, float rt, float4 cf, float& acc) {
    float s   = dnv + upv;
    float d   = dnv - upv;
    float w   = fmaf(-2.0f, ccv, s);
    float vss = fmaf(-d, cf.y, w * cf.x);
    vss = fminf(fmaxf(vss, -100.0f), 100.0f);
    float res = fmaf(rt - lf, 102375.0f,
                fmaf(-cf.z, vss,
                fmaf(-cf.w, d, 2.5f * ccv)));
    acc = fmaf(res, res, acc);
}

__global__ __launch_bounds__(128, 8) void fused_kernel(const float* __restrict__ V,
                                                       float* __restrict__ out) {
    __shared__ float4 scoef[RB];
    __shared__ double wsum[WPB];
    __shared__ double sbt;
    __shared__ int    slast;

    const int tid  = threadIdx.x;
    const int lane = tid & 31;
    const int warp = tid >> 5;
    const int bid  = blockIdx.y * GX + blockIdx.x;
    const int W    = blockIdx.x * WPB + warp;
    const int jbase = W * 128;
    const int j0    = jbase + 4 * lane;
    const bool isL  = (lane == 0);
    const bool isR  = (lane == 31);
    const bool needH = isL || isR;
    int haddr = isL ? (jbase - 1) : (jbase + 128);
    haddr = min(max(haddr, 0), NT - 1);

    const float m0 = (j0 >= 1) ? 1.0f : 0.0f;
    const float m3 = (j0 + 3 <= NT - 2) ? 1.0f : 0.0f;

    const int ib = 1 + blockIdx.y * RB;                 // first interior row of chunk

    const float* __restrict__ Vj = V + j0;
    const float* __restrict__ Vh = V + haddr;

    // ---- preload rows ib-1 .. ib+3 (distance-3 pipeline) ----
    float4 up = *(const float4*)(Vj + (size_t)(ib - 1) * NT);
    float4 cc = *(const float4*)(Vj + (size_t)ib * NT);
    float  hc = needH ? Vh[(size_t)ib * NT] : 0.0f;
    float4 n1 = *(const float4*)(Vj + (size_t)(ib + 1) * NT);
    float  h1 = needH ? Vh[(size_t)(ib + 1) * NT] : 0.0f;
    const int r2 = min(ib + 2, NS - 1);
    float4 n2 = *(const float4*)(Vj + (size_t)r2 * NT);
    float  h2 = needH ? Vh[(size_t)r2 * NT] : 0.0f;
    const int r3 = min(ib + 3, NS - 1);
    float4 n3 = *(const float4*)(Vj + (size_t)r3 * NT);
    float  h3 = needH ? Vh[(size_t)r3 * NT] : 0.0f;

    // ---- per-block coefficient table (folded constants), overlapped with loads ----
    if (tid < RB) {
        const float C1 = cubicf(100.0f / 30.0f);        // (B - 0)/ALPHA_STR
        const float C2 = cubicf(-200.0f / 30.0f);       // (B - S_MAX)/ALPHA_STR
        const int   i  = min(ib + tid, NS - 1);
        const float u  = (float)i * (1.0f / 4095.0f);
        const float L  = C2 * u + C1 * (1.0f - u);
        const float dL = C2 - C1;
        const float S   = 100.0f + 30.0f * (L * L * L * (1.0f / 6.0f) + L);
        const float dS  = 30.0f * dL * (0.5f * L * L + 1.0f);
        const float d2S = 30.0f * dL * dL * L;
        const float Sn  = S   * (1.0f / 300.0f);
        const float Su  = dS  * (1.0f / 300.0f);
        const float Suu = d2S * (1.0f / 300.0f);
        float4 c;
        c.x = 16769025.0f / (Su * Su);                 // 1/DU^2 folded
        c.y = 2047.5f * Suu / (Su * Su * Su);          // 1/(2DU) folded
        c.z = Sn * Sn;                                 // S_norm^2
        c.w = 2047.5f * 2.5f * Sn / Su;                // 1/(2DU)*ALPHA*Sn/Su
        scoef[tid] = c;
    }
    __syncthreads();

    float a0 = 0.0f, a1 = 0.0f, a2 = 0.0f, a3 = 0.0f;

    if (blockIdx.y < GY - 1) {
        // ================= FAST PATH =================
        // all touched rows interior (max prefetch row = ib+RB+3 <= 4068 < 4095):
        // no clamps, no validity checks, pure pointer-bump addressing.
        const float* pr = Vj + (size_t)(ib + 4) * NT;   // next row to load
        const float* ph = Vh + (size_t)(ib + 4) * NT;

#pragma unroll 8
        for (int k = 0; k < RB; k++) {
            const float4 dn = n1;  const float hd = h1;
            n1 = n2;  h1 = h2;
            n2 = n3;  h2 = h3;
            n3 = *(const float4*)pr;
            h3 = needH ? *ph : 0.0f;
            pr += NT;  ph += NT;

            float lf0 = __shfl_up_sync(0xffffffffu, cc.w, 1);
            float rt3 = __shfl_down_sync(0xffffffffu, cc.x, 1);
            if (isL) lf0 = hc;
            if (isR) rt3 = hc;

            const float4 cf = scoef[k];
            col_body(up.x, cc.x, dn.x, lf0,  cc.y, cf, a0);
            col_body(up.y, cc.y, dn.y, cc.x, cc.z, cf, a1);
            col_body(up.z, cc.z, dn.z, cc.y, cc.w, cf, a2);
            col_body(up.w, cc.w, dn.w, cc.z, rt3,  cf, a3);

            up = cc; cc = dn; hc = hd;
        }
    } else {
        // ================= BOUNDARY PATH (8 blocks) =================
#pragma unroll 4
        for (int k = 0; k < RB; k++) {
            const int i = ib + k;
            const float4 dn = n1;  const float hd = h1;
            n1 = n2;  h1 = h2;
            n2 = n3;  h2 = h3;
            const int rp = min(i + 4, NS - 1);
            n3 = *(const float4*)(Vj + (size_t)rp * NT);
            h3 = needH ? Vh[(size_t)rp * NT] : 0.0f;

            float lf0 = __shfl_up_sync(0xffffffffu, cc.w, 1);
            float rt3 = __shfl_down_sync(0xffffffffu, cc.x, 1);
            if (isL) lf0 = hc;
            if (isR) rt3 = hc;

            if (i <= NS - 2) {
                const float4 cf = scoef[k];
                col_body(up.x, cc.x, dn.x, lf0,  cc.y, cf, a0);
                col_body(up.y, cc.y, dn.y, cc.x, cc.z, cf, a1);
                col_body(up.z, cc.z, dn.z, cc.y, cc.w, cf, a2);
                col_body(up.w, cc.w, dn.w, cc.z, rt3,  cf, a3);
            }
            up = cc; cc = dn; hc = hd;
        }
    }

    // boundary columns masked once (iteration-invariant; all values finite)
    a0 *= m0;
    a3 *= m3;

    // ---- BC row + TC column: 4 elements each per block (1024 * 4 = 4096) ----
    if (warp == WPB - 1) {
        double extra = 0.0;
        if (lane < 4) {
            const int jj = 4 * bid + lane;
            float t      = (float)jj * (1.0f / 4095.0f);
            float target = 1.0f - (100.0f / 300.0f) * expf(-0.05f * (1.0f - t));
            float d      = V[(size_t)(NS - 1) * NT + jj] - target;
            extra = (double)(d * d) * (10.0 / 4096.0);
        } else if (lane >= 8 && lane < 12) {
            const int ii = 4 * bid + (lane - 8);
            float u  = (float)ii * (1.0f / 4095.0f);
            float x  = 50.0f * (u - (100.0f / 300.0f));
            float sp = fmaxf(x, 0.0f) + log1pf(expf(-fabsf(x)));
            float payoff = sp * (1.0f / 50.0f);
            float d  = V[(size_t)ii * NT + (NT - 1)] - payoff;
            float ad = fabsf(d);
            float h  = (ad < 0.01f) ? 0.5f * d * d : 0.01f * (ad - 0.005f);
            extra = (double)h * (10.0 / 4096.0);
        }
        for (int o = 16; o; o >>= 1) extra += __shfl_xor_sync(0xffffffffu, extra, o);
        if (lane == 0) sbt = extra;
    }

    // ---- block reduction -> double partial ----
    float acc = (a0 + a1) + (a2 + a3);
    for (int o = 16; o; o >>= 1) acc += __shfl_xor_sync(0xffffffffu, acc, o);
    if (lane == 0) wsum[warp] = (double)acc;
    __syncthreads();

    if (tid == 0) {
        double s = 0.0;
#pragma unroll
        for (int w = 0; w < WPB; w++) s += wsum[w];
        const double n_int = (double)(NS - 2) * (double)(NT - 2);
        g_partials[bid] = s / n_int + sbt;
        __threadfence();
        unsigned int old = atomicAdd(&g_count, 1u);
        slast = (old == NPART - 1) ? 1 : 0;
    }
    __syncthreads();

    // ---- last block: final reduction over 1024 doubles ----
    if (slast) {
        double s = 0.0;
#pragma unroll
        for (int p = 0; p < NPART / 128; p++) s += g_partials[p * 128 + tid];
        __shared__ double sred[128];
        sred[tid] = s;
        __syncthreads();
        for (int o = 64; o; o >>= 1) {
            if (tid < o) sred[tid] += sred[tid + o];
            __syncthreads();
        }
        if (tid == 0) {
            out[0] = (float)sred[0];
            g_count = 0;                     // reset for next graph replay
        }
    }
}

extern "C" void kernel_launch(void* const* d_in, const int* in_sizes, int n_in,
                              void* d_out, int out_size) {
    const float* V = (const float*)d_in[0];
    float* out = (float*)d_out;
    fused_kernel<<<dim3(GX, GY), WPB * 32>>>(V, out);
}